// round 15
// baseline (speedup 1.0000x reference)
#include <cuda_runtime.h>
#include <cstdint>
#include <float.h>

#define NB    4
#define NPTS  8192
#define NPQ   2048
#define NCH   128

// ---------------- device scratch (statically allocated; no cudaMalloc) ----------------
__device__ float4 g_p4[NB * NPTS];                    // (x,y,z,|p|^2)
__device__ int    g_fps[NB * NPQ];
__device__ int    g_ord[NB * NPTS];                   // morton-binned original indices
__device__ float4 g_cbmin[NB * 256], g_cbmax[NB * 256]; // 32-pt chunk bboxes (sorted order)
__device__ float4 g_sbmin[NB * 16],  g_sbmax[NB * 16];  // 512-pt super bboxes
__device__ float  g_feat_t[(size_t)NB * NPTS * NCH];  // features transposed [B,N,C]
__device__ float  g_coarse_t[(size_t)NB * NPQ * NCH]; // pooled features [B,q,C]
__device__ int    g_i3[NB * NPTS * 3];
__device__ float  g_w3[NB * NPTS * 3];

typedef unsigned long long u64;
__device__ u64 g_nn[(size_t)NB * NPTS * 24];          // three_nn partials: 8 chunks x 3 keys

// ---------------- packed f32x2 helpers ----------------
__device__ __forceinline__ u64 pk2(float a, float b) {
    u64 r; asm("mov.b64 %0, {%1,%2};" : "=l"(r) : "f"(a), "f"(b)); return r;
}
__device__ __forceinline__ void upk2(u64 v, float& a, float& b) {
    asm("mov.b64 {%0,%1}, %2;" : "=f"(a), "=f"(b) : "l"(v));
}
__device__ __forceinline__ u64 add2(u64 a, u64 b) {
    u64 r; asm("add.rn.f32x2 %0, %1, %2;" : "=l"(r) : "l"(a), "l"(b)); return r;
}
__device__ __forceinline__ u64 mul2(u64 a, u64 b) {
    u64 r; asm("mul.rn.f32x2 %0, %1, %2;" : "=l"(r) : "l"(a), "l"(b)); return r;
}
__device__ __forceinline__ u64 fma2(u64 a, u64 b, u64 c) {
    u64 r; asm("fma.rn.f32x2 %0, %1, %2, %3;" : "=l"(r) : "l"(a), "l"(b), "l"(c)); return r;
}
__device__ __forceinline__ float boxd2f(float4 q, float4 mn, float4 mx) {
    float dx = fmaxf(fmaxf(mn.x - q.x, q.x - mx.x), 0.f);
    float dy = fmaxf(fmaxf(mn.y - q.y, q.y - mx.y), 0.f);
    float dz = fmaxf(fmaxf(mn.z - q.z, q.z - mx.z), 0.f);
    return __fmaf_rn(dz, dz, __fmaf_rn(dy, dy, dx * dx));
}

// ---------------- merged prep + morton counting sort + chunk/super bboxes ----------------
__device__ __forceinline__ unsigned eb4(unsigned v) {  // 4 bits -> stride-3 positions
    return (v & 1u) | ((v & 2u) << 2) | ((v & 4u) << 4) | ((v & 8u) << 6);
}
__global__ void __launch_bounds__(1024, 1) prep_sort_kernel(const float* __restrict__ pts) {
    __shared__ unsigned hist[4096];
    __shared__ unsigned wsum[32];
    __shared__ float4 scn[256], scx[256];
    const int b = blockIdx.x, tid = threadIdx.x;
    const int lane = tid & 31, wid = tid >> 5;
    for (int i = tid; i < 4096; i += 1024) hist[i] = 0;
    __syncthreads();
    unsigned code[8];
#pragma unroll
    for (int k = 0; k < 8; k++) {
        int i = b * NPTS + tid + k * 1024;
        float x = pts[3 * i], y = pts[3 * i + 1], z = pts[3 * i + 2];
        float nr = __fmaf_rn(z, z, __fmaf_rn(y, y, x * x));
        g_p4[i] = make_float4(x, y, z, nr);
        unsigned mx = (unsigned)fminf(fmaxf((x + 4.f) * 2.f, 0.f), 15.f);
        unsigned my = (unsigned)fminf(fmaxf((y + 4.f) * 2.f, 0.f), 15.f);
        unsigned mz = (unsigned)fminf(fmaxf((z + 4.f) * 2.f, 0.f), 15.f);
        code[k] = eb4(mx) | (eb4(my) << 1) | (eb4(mz) << 2);
        atomicAdd(&hist[code[k]], 1u);
    }
    __syncthreads();
    unsigned h0 = hist[4 * tid], h1 = hist[4 * tid + 1],
             h2 = hist[4 * tid + 2], h3 = hist[4 * tid + 3];
    unsigned s = h0 + h1 + h2 + h3, si = s;
#pragma unroll
    for (int d = 1; d < 32; d <<= 1) {
        unsigned v = __shfl_up_sync(0xffffffffu, si, d);
        if (lane >= d) si += v;
    }
    if (lane == 31) wsum[wid] = si;
    __syncthreads();
    if (wid == 0) {
        unsigned v = wsum[lane], vi = v;
#pragma unroll
        for (int d = 1; d < 32; d <<= 1) {
            unsigned t = __shfl_up_sync(0xffffffffu, vi, d);
            if (lane >= d) vi += t;
        }
        wsum[lane] = vi;
    }
    __syncthreads();
    unsigned base = (wid ? wsum[wid - 1] : 0u) + si - s;
    hist[4 * tid]     = base;
    hist[4 * tid + 1] = base + h0;
    hist[4 * tid + 2] = base + h0 + h1;
    hist[4 * tid + 3] = base + h0 + h1 + h2;
    __syncthreads();
#pragma unroll
    for (int k = 0; k < 8; k++) {
        int i = tid + k * 1024;
        unsigned slot = atomicAdd(&hist[code[k]], 1u);
        g_ord[b * NPTS + slot] = i;
    }
    __syncthreads();                                  // all g_ord/g_p4 visible in block
    if (tid < 256) {                                  // chunk bboxes (32 sorted pts each)
        float4 mn = make_float4(FLT_MAX, FLT_MAX, FLT_MAX, 0.f);
        float4 mx = make_float4(-FLT_MAX, -FLT_MAX, -FLT_MAX, 0.f);
        for (int i = 0; i < 32; i++) {
            float4 p = g_p4[b * NPTS + g_ord[b * NPTS + tid * 32 + i]];
            mn.x = fminf(mn.x, p.x); mx.x = fmaxf(mx.x, p.x);
            mn.y = fminf(mn.y, p.y); mx.y = fmaxf(mx.y, p.y);
            mn.z = fminf(mn.z, p.z); mx.z = fmaxf(mx.z, p.z);
        }
        scn[tid] = mn; scx[tid] = mx;
        g_cbmin[b * 256 + tid] = mn; g_cbmax[b * 256 + tid] = mx;
    }
    __syncthreads();
    if (tid < 16) {                                   // super bboxes (16 chunks each)
        float4 mn = scn[tid * 16], mx = scx[tid * 16];
        for (int i = 1; i < 16; i++) {
            float4 a = scn[tid * 16 + i], c = scx[tid * 16 + i];
            mn.x = fminf(mn.x, a.x); mx.x = fmaxf(mx.x, c.x);
            mn.y = fminf(mn.y, a.y); mx.y = fmaxf(mx.y, c.y);
            mn.z = fminf(mn.z, a.z); mx.z = fmaxf(mx.z, c.z);
        }
        g_sbmin[b * 16 + tid] = mn; g_sbmax[b * 16 + tid] = mx;
    }
}

// ---------------- FPS: one CTA/batch, 512 threads x 16 pts, warp pruning (frozen) ----------------
__global__ void __launch_bounds__(512, 1) fps_kernel() {
    extern __shared__ char fsmem[];                   // sP 128KB | sOrd 32KB
    float4* sP   = (float4*)fsmem;
    int*    sOrd = (int*)(fsmem + NPTS * sizeof(float4));
    const int b    = blockIdx.x;
    const int tid  = threadIdx.x;
    const int lane = tid & 31;
    const int wid  = tid >> 5;
    const float4* __restrict__ P = g_p4 + b * NPTS;

#pragma unroll
    for (int k = 0; k < 16; k++) {
        sP[tid + k * 512]   = P[tid + k * 512];
        sOrd[tid + k * 512] = g_ord[b * NPTS + tid + k * 512];
    }
    __shared__ u64 skey[2][16];
    if (tid == 0) g_fps[b * NPQ] = 0;
    __syncthreads();

    const int wbase = wid * 512 + lane * 2;
    u64 X[8], Y[8], Z[8];
    float dist[16];
    unsigned ordp[8];
    float blx = FLT_MAX, bhx = -FLT_MAX, bly = FLT_MAX, bhy = -FLT_MAX,
          blz = FLT_MAX, bhz = -FLT_MAX;
#pragma unroll
    for (int i = 0; i < 8; i++) {
        int o0 = sOrd[wbase + i * 64], o1 = sOrd[wbase + i * 64 + 1];
        ordp[i] = (unsigned)o0 | ((unsigned)o1 << 16);
        float4 a = sP[o0], c = sP[o1];
        X[i] = pk2(a.x, c.x); Y[i] = pk2(a.y, c.y); Z[i] = pk2(a.z, c.z);
        blx = fminf(blx, fminf(a.x, c.x)); bhx = fmaxf(bhx, fmaxf(a.x, c.x));
        bly = fminf(bly, fminf(a.y, c.y)); bhy = fmaxf(bhy, fmaxf(a.y, c.y));
        blz = fminf(blz, fminf(a.z, c.z)); bhz = fmaxf(bhz, fmaxf(a.z, c.z));
    }
#pragma unroll
    for (int s = 16; s > 0; s >>= 1) {
        blx = fminf(blx, __shfl_xor_sync(0xffffffffu, blx, s));
        bhx = fmaxf(bhx, __shfl_xor_sync(0xffffffffu, bhx, s));
        bly = fminf(bly, __shfl_xor_sync(0xffffffffu, bly, s));
        bhy = fmaxf(bhy, __shfl_xor_sync(0xffffffffu, bhy, s));
        blz = fminf(blz, __shfl_xor_sync(0xffffffffu, blz, s));
        bhz = fmaxf(bhz, __shfl_xor_sync(0xffffffffu, bhz, s));
    }

    u64 mykey;
    float wmaxf;
    {   // iteration 0: d0 = ||x - x0||^2
        float4 q0 = sP[0];
        u64 ax = pk2(-q0.x, -q0.x), ay = pk2(-q0.y, -q0.y), az = pk2(-q0.z, -q0.z);
#pragma unroll
        for (int i = 0; i < 8; i++) {
            u64 dx = add2(X[i], ax), dy = add2(Y[i], ay), dz = add2(Z[i], az);
            u64 t = fma2(dz, dz, fma2(dy, dy, mul2(dx, dx)));
            upk2(t, dist[2 * i], dist[2 * i + 1]);
        }
        float tmax = dist[0];
#pragma unroll
        for (int k = 1; k < 16; k++) tmax = fmaxf(tmax, dist[k]);
        unsigned wm = __reduce_max_sync(0xffffffffu, __float_as_uint(tmax));
        wmaxf = __uint_as_float(wm);
        unsigned cand = 0xffffffffu;
#pragma unroll
        for (int k = 0; k < 16; k++) {
            unsigned oi = (k & 1) ? (ordp[k >> 1] >> 16) : (ordp[k >> 1] & 0xffffu);
            if (dist[k] == wmaxf) cand = min(cand, oi);
        }
        unsigned widx = __reduce_min_sync(0xffffffffu, cand);
        mykey = ((u64)wm << 32) | widx;
        if (lane == 0) skey[0][wid] = mykey;
    }

    for (int j = 1; j < NPQ; j++) {
        __syncthreads();
        u64 k64 = skey[(j - 1) & 1][lane & 15];
        unsigned hi = (unsigned)(k64 >> 32), lo = (unsigned)k64;
        unsigned g   = __reduce_max_sync(0xffffffffu, hi);
        unsigned cc  = (hi == g) ? lo : 0xffffffffu;
        unsigned nxt = __reduce_min_sync(0xffffffffu, cc);
        if (tid == 0) g_fps[b * NPQ + j] = (int)nxt;

        float4 qq = sP[nxt];
        float dxb = fmaxf(fmaxf(blx - qq.x, qq.x - bhx), 0.f);
        float dyb = fmaxf(fmaxf(bly - qq.y, qq.y - bhy), 0.f);
        float dzb = fmaxf(fmaxf(blz - qq.z, qq.z - bhz), 0.f);
        float boxd2 = __fmaf_rn(dzb, dzb, __fmaf_rn(dyb, dyb, dxb * dxb));

        if (boxd2 < wmaxf * 1.00001f) {
            u64 ax = pk2(-qq.x, -qq.x), ay = pk2(-qq.y, -qq.y), az = pk2(-qq.z, -qq.z);
#pragma unroll
            for (int i = 0; i < 8; i++) {
                u64 dx = add2(X[i], ax), dy = add2(Y[i], ay), dz = add2(Z[i], az);
                u64 t = fma2(dz, dz, fma2(dy, dy, mul2(dx, dx)));
                float a, c; upk2(t, a, c);
                dist[2 * i]     = fminf(dist[2 * i], a);
                dist[2 * i + 1] = fminf(dist[2 * i + 1], c);
            }
            float tmax = dist[0];
#pragma unroll
            for (int k = 1; k < 16; k++) tmax = fmaxf(tmax, dist[k]);
            unsigned wm = __reduce_max_sync(0xffffffffu, __float_as_uint(tmax));
            wmaxf = __uint_as_float(wm);
            unsigned cand = 0xffffffffu;
#pragma unroll
            for (int k = 0; k < 16; k++) {
                unsigned oi = (k & 1) ? (ordp[k >> 1] >> 16) : (ordp[k >> 1] & 0xffffu);
                if (dist[k] == wmaxf) cand = min(cand, oi);
            }
            unsigned widx = __reduce_min_sync(0xffffffffu, cand);
            mykey = ((u64)wm << 32) | widx;
        }
        if (lane == 0) skey[j & 1][wid] = mykey;
    }
}

// ---------------- transpose features [B,C,N] -> [B,N,C] ----------------
__global__ void transpose_kernel(const float* __restrict__ f) {
    __shared__ float tile[32][33];
    int b = blockIdx.z;
    int c0 = blockIdx.y * 32, n0 = blockIdx.x * 32;
    tile[threadIdx.y][threadIdx.x] =
        f[((size_t)b * NCH + c0 + threadIdx.y) * NPTS + n0 + threadIdx.x];
    __syncthreads();
    g_feat_t[((size_t)b * NPTS + n0 + threadIdx.y) * NCH + c0 + threadIdx.x] =
        tile[threadIdx.x][threadIdx.y];
}

// ---------------- kNN: chunk-bbox pruned warp top-17 + mean-pool ----------------
// Points scanned in morton-sorted order; exact u64 lex keys (sqbits, origidx)
// make the top-17 SET order-independent; outer admit is sq <= thr so equal-
// distance smaller-index candidates always reach the exact inner compare.
// Box skips use conservative margin thr*1.00001 (>> fp rounding) -> never
// skips a true top-17 member. Pool runs ranks 1..16 ascending = reference
// top_k order -> bit-identical sums.
__device__ __forceinline__ void knn_scan_chunk(
    const float4* sT, const int* sIdx, int cc, float4 q,
    u64& mykey, float& thr_f, int lane
) {
    int slot = cc * 32 + lane;
    float4 p = sT[slot];
    float dot = __fmaf_rn(q.z, p.z, __fmaf_rn(q.y, p.y, q.x * p.x));
    float sq  = fmaxf(__fmaf_rn(-2.f, dot, q.w + p.w), 0.f);
    unsigned ball = __ballot_sync(0xffffffffu, sq <= thr_f);
    if (ball) {
        u64 cand = ((u64)__float_as_uint(sq) << 32) | (unsigned)sIdx[slot];
        do {
            int src = __ffs(ball) - 1; ball &= ball - 1;
            u64 c = __shfl_sync(0xffffffffu, cand, src);
            unsigned pb = __ballot_sync(0xffffffffu, (lane < 17) && (c < mykey));
            if (pb) {
                int pos = __ffs(pb) - 1;
                u64 up = __shfl_up_sync(0xffffffffu, mykey, 1);
                if (lane >= pos && lane < 17) mykey = (lane == pos) ? c : up;
            }
        } while (ball);
        thr_f = __uint_as_float(__shfl_sync(0xffffffffu, (unsigned)(mykey >> 32), 16));
    }
}

__global__ void __launch_bounds__(1024) knn_group_kernel() {
    extern __shared__ char ksmem[];
    float4* sT   = (float4*)ksmem;                          // 128KB sorted points
    int*    sIdx = (int*)(ksmem + 131072);                  // 32KB orig indices
    float4* scn  = (float4*)(ksmem + 163840);               // 4KB chunk mins
    float4* scx  = (float4*)(ksmem + 167936);               // 4KB chunk maxs
    float4* ssn  = (float4*)(ksmem + 172032);               // 256B super mins
    float4* ssx  = (float4*)(ksmem + 172288);               // 256B super maxs
    const int tid  = threadIdx.x;
    const int lane = tid & 31;
    const int w    = tid >> 5;                              // 0..31
    const int b    = blockIdx.x >> 5;
    const int qb   = (blockIdx.x & 31) * 64;

#pragma unroll
    for (int k = 0; k < 8; k++) {
        int s = tid + k * 1024;
        int o = g_ord[b * NPTS + s];
        sT[s]   = g_p4[b * NPTS + o];
        sIdx[s] = o;
    }
    if (tid < 256) { scn[tid] = g_cbmin[b * 256 + tid]; scx[tid] = g_cbmax[b * 256 + tid]; }
    if (tid < 16)  { ssn[tid] = g_sbmin[b * 16 + tid];  ssx[tid] = g_sbmax[b * 16 + tid]; }
    __syncthreads();

    const float* Fb = g_feat_t + (size_t)b * NPTS * NCH;
    for (int qi = 0; qi < 2; qi++) {
        int gw = b * NPQ + qb + w * 2 + qi;
        float4 q = g_p4[b * NPTS + g_fps[gw]];
        u64 mykey = 0x7F7FFFFFFFFFFFFFull;                  // (FLT_MAX, ~0)
        float thr_f = FLT_MAX;

        // per-lane super distance (lanes 16-31 duplicate lanes 0-15)
        float sdist = boxd2f(q, ssn[lane & 15], ssx[lane & 15]);
        unsigned sd32 = __float_as_uint(sdist);
        unsigned gmin = __reduce_min_sync(0xffffffffu, sd32);
        unsigned best = __reduce_min_sync(0xffffffffu,
                            (sd32 == gmin) ? (unsigned)(lane & 15) : 32u);

        // pass 1: scan nearest super fully (tightens thr)
#pragma unroll 1
        for (int c = 0; c < 16; c++)
            knn_scan_chunk(sT, sIdx, (int)best * 16 + c, q, mykey, thr_f, lane);

        // pass 2: remaining supers with box skips
#pragma unroll 1
        for (int s = 0; s < 16; s++) {
            if (s == (int)best) continue;
            float sd = __shfl_sync(0xffffffffu, sdist, s);
            if (sd > thr_f * 1.00001f) continue;
            float cd = (lane < 16) ? boxd2f(q, scn[s * 16 + lane], scx[s * 16 + lane])
                                   : FLT_MAX;
            unsigned cm = __ballot_sync(0xffffffffu, cd <= thr_f * 1.00001f);
            while (cm) {
                int c = __ffs(cm) - 1; cm &= cm - 1;
                knn_scan_chunk(sT, sIdx, s * 16 + c, q, mykey, thr_f, lane);
            }
        }

        // mean-pool: ranks 1..16 ascending; loads batched (MLP=4), adds sequential
        float4 acc = make_float4(0.f, 0.f, 0.f, 0.f);
#pragma unroll
        for (int r = 1; r < 17; r += 4) {
            int n0 = (int)(unsigned)__shfl_sync(0xffffffffu, mykey, r);
            int n1 = (int)(unsigned)__shfl_sync(0xffffffffu, mykey, r + 1);
            int n2 = (int)(unsigned)__shfl_sync(0xffffffffu, mykey, r + 2);
            int n3 = (int)(unsigned)__shfl_sync(0xffffffffu, mykey, r + 3);
            float4 f0 = ((const float4*)(Fb + (size_t)n0 * NCH))[lane];
            float4 f1 = ((const float4*)(Fb + (size_t)n1 * NCH))[lane];
            float4 f2 = ((const float4*)(Fb + (size_t)n2 * NCH))[lane];
            float4 f3 = ((const float4*)(Fb + (size_t)n3 * NCH))[lane];
            acc.x += f0.x; acc.y += f0.y; acc.z += f0.z; acc.w += f0.w;
            acc.x += f1.x; acc.y += f1.y; acc.z += f1.z; acc.w += f1.w;
            acc.x += f2.x; acc.y += f2.y; acc.z += f2.z; acc.w += f2.w;
            acc.x += f3.x; acc.y += f3.y; acc.z += f3.z; acc.w += f3.w;
        }
        float4 o = make_float4(acc.x * 0.0625f, acc.y * 0.0625f,
                               acc.z * 0.0625f, acc.w * 0.0625f);
        ((float4*)(g_coarse_t + (size_t)gw * NCH))[lane] = o;
    }
}

// ---------------- three_nn part: 8 chunks x 256 queries, lex top-3, fused gather ----------------
__global__ void __launch_bounds__(256) three_nn_part() {
    int b = blockIdx.y, c = blockIdx.z;
    int n = blockIdx.x * 256 + threadIdx.x;
    __shared__ float4 sq4[256];
    sq4[threadIdx.x] = g_p4[b * NPTS + g_fps[b * NPQ + c * 256 + threadIdx.x]];
    __syncthreads();

    float4 p = g_p4[b * NPTS + n];
    u64 k0 = ~0ull, k1 = ~0ull, k2 = ~0ull;
    for (int j2 = 0; j2 < 256; j2++) {
        float4 q = sq4[j2];
        float dot = __fmaf_rn(q.z, p.z, __fmaf_rn(q.y, p.y, q.x * p.x));
        float s   = fmaxf(__fmaf_rn(-2.f, dot, q.w + p.w), 0.f);
        u64 key = ((u64)__float_as_uint(s) << 32) | (unsigned)(c * 256 + j2);
        if (key < k2) {
            if (key < k0)      { k2 = k1; k1 = k0; k0 = key; }
            else if (key < k1) { k2 = k1; k1 = key; }
            else               { k2 = key; }
        }
    }
    size_t o = ((size_t)(b * NPTS + n) * 8 + c) * 3;
    g_nn[o] = k0; g_nn[o + 1] = k1; g_nn[o + 2] = k2;
}

// ---------------- three_nn combine: merge 8 chunks, compute weights ----------------
__global__ void __launch_bounds__(256) three_nn_comb() {
    int i = blockIdx.x * 256 + threadIdx.x;           // over NB*NPTS
    u64 a0 = ~0ull, a1 = ~0ull, a2 = ~0ull;
#pragma unroll
    for (int c = 0; c < 24; c++) {
        u64 k = g_nn[(size_t)i * 24 + c];
        if (k < a0)      { a2 = a1; a1 = a0; a0 = k; }
        else if (k < a1) { a2 = a1; a1 = k; }
        else if (k < a2) { a2 = k; }
    }
    float d0 = fmaxf(__uint_as_float((unsigned)(a0 >> 32)), 1e-10f);
    float d1 = fmaxf(__uint_as_float((unsigned)(a1 >> 32)), 1e-10f);
    float d2 = fmaxf(__uint_as_float((unsigned)(a2 >> 32)), 1e-10f);
    float v0 = __fdiv_rn(1.f, d0 + 1e-8f);
    float v1 = __fdiv_rn(1.f, d1 + 1e-8f);
    float v2 = __fdiv_rn(1.f, d2 + 1e-8f);
    float ss = v0 + v1 + v2;
    int o = i * 3;
    g_i3[o] = (int)(unsigned)a0; g_i3[o + 1] = (int)(unsigned)a1; g_i3[o + 2] = (int)(unsigned)a2;
    g_w3[o]     = __fdiv_rn(v0, ss);
    g_w3[o + 1] = __fdiv_rn(v1, ss);
    g_w3[o + 2] = __fdiv_rn(v2, ss);
}

// ---------------- interpolate: smem-staged, coalesced channel-major stores ----------------
__global__ void __launch_bounds__(256) interp_kernel(float* __restrict__ out) {
    __shared__ float tile[32 * 129];
    int b    = blockIdx.y;
    int n0   = blockIdx.x * 32;
    int lane = threadIdx.x & 31;
    int w    = threadIdx.x >> 5;

#pragma unroll
    for (int k = 0; k < 4; k++) {
        int nl = w * 4 + k;
        int n  = n0 + nl;
        int o = (b * NPTS + n) * 3;
        int a0 = g_i3[o], a1 = g_i3[o + 1], a2 = g_i3[o + 2];
        float w0 = g_w3[o], w1 = g_w3[o + 1], w2 = g_w3[o + 2];

        const float4* C = (const float4*)g_coarse_t + (size_t)b * NPQ * (NCH / 4);
        float4 f0 = C[a0 * (NCH / 4) + lane];
        float4 f1 = C[a1 * (NCH / 4) + lane];
        float4 f2 = C[a2 * (NCH / 4) + lane];

        float4 r;
        r.x = __fmaf_rn(f2.x, w2, __fmaf_rn(f1.x, w1, f0.x * w0));
        r.y = __fmaf_rn(f2.y, w2, __fmaf_rn(f1.y, w1, f0.y * w0));
        r.z = __fmaf_rn(f2.z, w2, __fmaf_rn(f1.z, w1, f0.z * w0));
        r.w = __fmaf_rn(f2.w, w2, __fmaf_rn(f1.w, w1, f0.w * w0));

        float* trow = tile + nl * 129 + lane * 4;
        trow[0] = r.x; trow[1] = r.y; trow[2] = r.z; trow[3] = r.w;
    }
    __syncthreads();

    float* ob = out + (size_t)b * NCH * NPTS + n0;
#pragma unroll
    for (int pass = 0; pass < 16; pass++) {
        int c = pass * 8 + w;
        ob[(size_t)c * NPTS + lane] = tile[lane * 129 + c];
    }
}

// ---------------- launch ----------------
extern "C" void kernel_launch(void* const* d_in, const int* in_sizes, int n_in,
                              void* d_out, int out_size) {
    const float* points   = (const float*)d_in[0];
    const float* features = (const float*)d_in[1];
    for (int i = 0; i < n_in; i++) {
        if (in_sizes[i] == NB * NPTS * 3)            points   = (const float*)d_in[i];
        else if (in_sizes[i] == NB * NCH * NPTS)     features = (const float*)d_in[i];
    }
    float* out = (float*)d_out;

    const int fps_smem = NPTS * (int)sizeof(float4) + NPTS * (int)sizeof(int); // 160KB
    const int knn_smem = 172544;                                               // 168.5KB
    cudaFuncSetAttribute(fps_kernel,       cudaFuncAttributeMaxDynamicSharedMemorySize, fps_smem);
    cudaFuncSetAttribute(knn_group_kernel, cudaFuncAttributeMaxDynamicSharedMemorySize, knn_smem);

    prep_sort_kernel<<<NB, 1024>>>(points);                                 // 1
    transpose_kernel<<<dim3(NPTS / 32, NCH / 32, NB), dim3(32, 32)>>>(features); // 2
    fps_kernel<<<NB, 512, fps_smem>>>();                                    // 3
    knn_group_kernel<<<128, 1024, knn_smem>>>();                            // 4 <- profiled
    three_nn_part<<<dim3(NPTS / 256, NB, 8), 256>>>();                      // 5
    three_nn_comb<<<(NB * NPTS) / 256, 256>>>();                            // 6
    interp_kernel<<<dim3(NPTS / 32, NB), 256>>>(out);                       // 7
}

// round 16
// speedup vs baseline: 1.0632x; 1.0632x over previous
#include <cuda_runtime.h>
#include <cstdint>
#include <float.h>

#define NB    4
#define NPTS  8192
#define NPQ   2048
#define NCH   128

// ---------------- device scratch (statically allocated; no cudaMalloc) ----------------
__device__ float4 g_p4[NB * NPTS];                    // (x,y,z,|p|^2)
__device__ int    g_fps[NB * NPQ];
__device__ int    g_ord[NB * NPTS];                   // morton-binned original indices
__device__ float  g_feat_t[(size_t)NB * NPTS * NCH];  // features transposed [B,N,C]
__device__ float  g_coarse_t[(size_t)NB * NPQ * NCH]; // pooled features [B,q,C]
__device__ int    g_i3[NB * NPTS * 3];
__device__ float  g_w3[NB * NPTS * 3];

typedef unsigned long long u64;
__device__ u64 g_nn[(size_t)NB * NPTS * 12];          // three_nn partials: 4 chunks x 3 keys

// ---------------- packed f32x2 helpers ----------------
__device__ __forceinline__ u64 pk2(float a, float b) {
    u64 r; asm("mov.b64 %0, {%1,%2};" : "=l"(r) : "f"(a), "f"(b)); return r;
}
__device__ __forceinline__ void upk2(u64 v, float& a, float& b) {
    asm("mov.b64 {%0,%1}, %2;" : "=f"(a), "=f"(b) : "l"(v));
}
__device__ __forceinline__ u64 add2(u64 a, u64 b) {
    u64 r; asm("add.rn.f32x2 %0, %1, %2;" : "=l"(r) : "l"(a), "l"(b)); return r;
}
__device__ __forceinline__ u64 mul2(u64 a, u64 b) {
    u64 r; asm("mul.rn.f32x2 %0, %1, %2;" : "=l"(r) : "l"(a), "l"(b)); return r;
}
__device__ __forceinline__ u64 fma2(u64 a, u64 b, u64 c) {
    u64 r; asm("fma.rn.f32x2 %0, %1, %2, %3;" : "=l"(r) : "l"(a), "l"(b), "l"(c)); return r;
}

// ---------------- merged prep + morton counting sort (one CTA per batch) ----------------
__device__ __forceinline__ unsigned eb4(unsigned v) {  // 4 bits -> stride-3 positions
    return (v & 1u) | ((v & 2u) << 2) | ((v & 4u) << 4) | ((v & 8u) << 6);
}
__global__ void __launch_bounds__(1024, 1) prep_sort_kernel(const float* __restrict__ pts) {
    __shared__ unsigned hist[4096];
    __shared__ unsigned wsum[32];
    const int b = blockIdx.x, tid = threadIdx.x;
    const int lane = tid & 31, wid = tid >> 5;
    for (int i = tid; i < 4096; i += 1024) hist[i] = 0;
    __syncthreads();
    unsigned code[8];
#pragma unroll
    for (int k = 0; k < 8; k++) {
        int i = b * NPTS + tid + k * 1024;
        float x = pts[3 * i], y = pts[3 * i + 1], z = pts[3 * i + 2];
        float nr = __fmaf_rn(z, z, __fmaf_rn(y, y, x * x));
        g_p4[i] = make_float4(x, y, z, nr);
        unsigned mx = (unsigned)fminf(fmaxf((x + 4.f) * 2.f, 0.f), 15.f);
        unsigned my = (unsigned)fminf(fmaxf((y + 4.f) * 2.f, 0.f), 15.f);
        unsigned mz = (unsigned)fminf(fmaxf((z + 4.f) * 2.f, 0.f), 15.f);
        code[k] = eb4(mx) | (eb4(my) << 1) | (eb4(mz) << 2);
        atomicAdd(&hist[code[k]], 1u);
    }
    __syncthreads();
    unsigned h0 = hist[4 * tid], h1 = hist[4 * tid + 1],
             h2 = hist[4 * tid + 2], h3 = hist[4 * tid + 3];
    unsigned s = h0 + h1 + h2 + h3, si = s;
#pragma unroll
    for (int d = 1; d < 32; d <<= 1) {
        unsigned v = __shfl_up_sync(0xffffffffu, si, d);
        if (lane >= d) si += v;
    }
    if (lane == 31) wsum[wid] = si;
    __syncthreads();
    if (wid == 0) {
        unsigned v = wsum[lane], vi = v;
#pragma unroll
        for (int d = 1; d < 32; d <<= 1) {
            unsigned t = __shfl_up_sync(0xffffffffu, vi, d);
            if (lane >= d) vi += t;
        }
        wsum[lane] = vi;
    }
    __syncthreads();
    unsigned base = (wid ? wsum[wid - 1] : 0u) + si - s;
    hist[4 * tid]     = base;
    hist[4 * tid + 1] = base + h0;
    hist[4 * tid + 2] = base + h0 + h1;
    hist[4 * tid + 3] = base + h0 + h1 + h2;
    __syncthreads();
#pragma unroll
    for (int k = 0; k < 8; k++) {
        int i = tid + k * 1024;
        unsigned slot = atomicAdd(&hist[code[k]], 1u);
        g_ord[b * NPTS + slot] = i;
    }
}

// ---------------- FPS: one CTA/batch, 512 threads x 16 pts, warp pruning (frozen) ----------------
__global__ void __launch_bounds__(512, 1) fps_kernel() {
    extern __shared__ char fsmem[];                   // sP 128KB | sOrd 32KB
    float4* sP   = (float4*)fsmem;
    int*    sOrd = (int*)(fsmem + NPTS * sizeof(float4));
    const int b    = blockIdx.x;
    const int tid  = threadIdx.x;
    const int lane = tid & 31;
    const int wid  = tid >> 5;                        // 0..15
    const float4* __restrict__ P = g_p4 + b * NPTS;

#pragma unroll
    for (int k = 0; k < 16; k++) {
        sP[tid + k * 512]   = P[tid + k * 512];
        sOrd[tid + k * 512] = g_ord[b * NPTS + tid + k * 512];
    }
    __shared__ u64 skey[2][16];
    if (tid == 0) g_fps[b * NPQ] = 0;
    __syncthreads();

    const int wbase = wid * 512 + lane * 2;
    u64 X[8], Y[8], Z[8];
    float dist[16];
    unsigned ordp[8];
    float blx = FLT_MAX, bhx = -FLT_MAX, bly = FLT_MAX, bhy = -FLT_MAX,
          blz = FLT_MAX, bhz = -FLT_MAX;
#pragma unroll
    for (int i = 0; i < 8; i++) {
        int o0 = sOrd[wbase + i * 64], o1 = sOrd[wbase + i * 64 + 1];
        ordp[i] = (unsigned)o0 | ((unsigned)o1 << 16);
        float4 a = sP[o0], c = sP[o1];
        X[i] = pk2(a.x, c.x); Y[i] = pk2(a.y, c.y); Z[i] = pk2(a.z, c.z);
        blx = fminf(blx, fminf(a.x, c.x)); bhx = fmaxf(bhx, fmaxf(a.x, c.x));
        bly = fminf(bly, fminf(a.y, c.y)); bhy = fmaxf(bhy, fmaxf(a.y, c.y));
        blz = fminf(blz, fminf(a.z, c.z)); bhz = fmaxf(bhz, fmaxf(a.z, c.z));
    }
#pragma unroll
    for (int s = 16; s > 0; s >>= 1) {
        blx = fminf(blx, __shfl_xor_sync(0xffffffffu, blx, s));
        bhx = fmaxf(bhx, __shfl_xor_sync(0xffffffffu, bhx, s));
        bly = fminf(bly, __shfl_xor_sync(0xffffffffu, bly, s));
        bhy = fmaxf(bhy, __shfl_xor_sync(0xffffffffu, bhy, s));
        blz = fminf(blz, __shfl_xor_sync(0xffffffffu, blz, s));
        bhz = fmaxf(bhz, __shfl_xor_sync(0xffffffffu, bhz, s));
    }

    u64 mykey;
    float wmaxf;
    {   // iteration 0: d0 = ||x - x0||^2
        float4 q0 = sP[0];
        u64 ax = pk2(-q0.x, -q0.x), ay = pk2(-q0.y, -q0.y), az = pk2(-q0.z, -q0.z);
#pragma unroll
        for (int i = 0; i < 8; i++) {
            u64 dx = add2(X[i], ax), dy = add2(Y[i], ay), dz = add2(Z[i], az);
            u64 t = fma2(dz, dz, fma2(dy, dy, mul2(dx, dx)));
            upk2(t, dist[2 * i], dist[2 * i + 1]);
        }
        float tmax = dist[0];
#pragma unroll
        for (int k = 1; k < 16; k++) tmax = fmaxf(tmax, dist[k]);
        unsigned wm = __reduce_max_sync(0xffffffffu, __float_as_uint(tmax));
        wmaxf = __uint_as_float(wm);
        unsigned cand = 0xffffffffu;
#pragma unroll
        for (int k = 0; k < 16; k++) {
            unsigned oi = (k & 1) ? (ordp[k >> 1] >> 16) : (ordp[k >> 1] & 0xffffu);
            if (dist[k] == wmaxf) cand = min(cand, oi);
        }
        unsigned widx = __reduce_min_sync(0xffffffffu, cand);
        mykey = ((u64)wm << 32) | widx;
        if (lane == 0) skey[0][wid] = mykey;
    }

    for (int j = 1; j < NPQ; j++) {
        __syncthreads();
        u64 k64 = skey[(j - 1) & 1][lane & 15];
        unsigned hi = (unsigned)(k64 >> 32), lo = (unsigned)k64;
        unsigned g   = __reduce_max_sync(0xffffffffu, hi);
        unsigned cc  = (hi == g) ? lo : 0xffffffffu;
        unsigned nxt = __reduce_min_sync(0xffffffffu, cc);
        if (tid == 0) g_fps[b * NPQ + j] = (int)nxt;

        float4 qq = sP[nxt];
        float dxb = fmaxf(fmaxf(blx - qq.x, qq.x - bhx), 0.f);
        float dyb = fmaxf(fmaxf(bly - qq.y, qq.y - bhy), 0.f);
        float dzb = fmaxf(fmaxf(blz - qq.z, qq.z - bhz), 0.f);
        float boxd2 = __fmaf_rn(dzb, dzb, __fmaf_rn(dyb, dyb, dxb * dxb));

        if (boxd2 < wmaxf * 1.00001f) {
            u64 ax = pk2(-qq.x, -qq.x), ay = pk2(-qq.y, -qq.y), az = pk2(-qq.z, -qq.z);
#pragma unroll
            for (int i = 0; i < 8; i++) {
                u64 dx = add2(X[i], ax), dy = add2(Y[i], ay), dz = add2(Z[i], az);
                u64 t = fma2(dz, dz, fma2(dy, dy, mul2(dx, dx)));
                float a, c; upk2(t, a, c);
                dist[2 * i]     = fminf(dist[2 * i], a);
                dist[2 * i + 1] = fminf(dist[2 * i + 1], c);
            }
            float tmax = dist[0];
#pragma unroll
            for (int k = 1; k < 16; k++) tmax = fmaxf(tmax, dist[k]);
            unsigned wm = __reduce_max_sync(0xffffffffu, __float_as_uint(tmax));
            wmaxf = __uint_as_float(wm);
            unsigned cand = 0xffffffffu;
#pragma unroll
            for (int k = 0; k < 16; k++) {
                unsigned oi = (k & 1) ? (ordp[k >> 1] >> 16) : (ordp[k >> 1] & 0xffffu);
                if (dist[k] == wmaxf) cand = min(cand, oi);
            }
            unsigned widx = __reduce_min_sync(0xffffffffu, cand);
            mykey = ((u64)wm << 32) | widx;
        }
        if (lane == 0) skey[j & 1][wid] = mykey;
    }
}

// ---------------- transpose features [B,C,N] -> [B,N,C] ----------------
__global__ void transpose_kernel(const float* __restrict__ f) {
    __shared__ float tile[32][33];
    int b = blockIdx.z;
    int c0 = blockIdx.y * 32, n0 = blockIdx.x * 32;
    tile[threadIdx.y][threadIdx.x] =
        f[((size_t)b * NCH + c0 + threadIdx.y) * NPTS + n0 + threadIdx.x];
    __syncthreads();
    g_feat_t[((size_t)b * NPTS + n0 + threadIdx.y) * NCH + c0 + threadIdx.x] =
        tile[threadIdx.x][threadIdx.y];
}

// ---------------- kNN: warp-shared sorted top-17 + mean-pool (32 warps/CTA) ----------------
// (R14 version: dense scan, 72% issue — proven faster than pruned variants)
__global__ void __launch_bounds__(1024) knn_group_kernel() {
    extern __shared__ float4 sT[];                    // 8192 float4 = 128KB
    const int tid  = threadIdx.x;
    const int lane = tid & 31;
    const int w    = tid >> 5;                        // 0..31
    const int b    = blockIdx.x >> 5;
    const int qb   = (blockIdx.x & 31) * 64;

#pragma unroll
    for (int k = 0; k < 8; k++) sT[tid + k * 1024] = g_p4[b * NPTS + tid + k * 1024];
    __syncthreads();

    const float* Fb = g_feat_t + (size_t)b * NPTS * NCH;
    for (int qi = 0; qi < 2; qi++) {
        int gw = b * NPQ + qb + w * 2 + qi;
        float4 q = sT[g_fps[gw]];
        u64 mykey = 0x7F7FFFFFFFFFFFFFull;            // (FLT_MAX, ~0)
        float thr_f = FLT_MAX;
        for (int t = 0; t < NPTS / 32; t++) {
            int n = t * 32 + lane;
            float4 p = sT[n];
            float dot = __fmaf_rn(q.z, p.z, __fmaf_rn(q.y, p.y, q.x * p.x));
            float sq  = fmaxf(__fmaf_rn(-2.f, dot, q.w + p.w), 0.f);
            unsigned ball = __ballot_sync(0xffffffffu, sq < thr_f);
            if (ball) {
                u64 cand = ((u64)__float_as_uint(sq) << 32) | (unsigned)n;
                do {
                    int src = __ffs(ball) - 1; ball &= ball - 1;
                    u64 c = __shfl_sync(0xffffffffu, cand, src);
                    unsigned pb = __ballot_sync(0xffffffffu, (lane < 17) && (c < mykey));
                    if (pb) {
                        int pos = __ffs(pb) - 1;
                        u64 up = __shfl_up_sync(0xffffffffu, mykey, 1);
                        if (lane >= pos && lane < 17) mykey = (lane == pos) ? c : up;
                    }
                } while (ball);
                thr_f = __uint_as_float(
                    __shfl_sync(0xffffffffu, (unsigned)(mykey >> 32), 16));
            }
        }
        // mean-pool: ascending-distance order; loads batched (MLP=4), adds sequential
        float4 acc = make_float4(0.f, 0.f, 0.f, 0.f);
#pragma unroll
        for (int r = 1; r < 17; r += 4) {
            int n0 = (int)(unsigned)__shfl_sync(0xffffffffu, mykey, r);
            int n1 = (int)(unsigned)__shfl_sync(0xffffffffu, mykey, r + 1);
            int n2 = (int)(unsigned)__shfl_sync(0xffffffffu, mykey, r + 2);
            int n3 = (int)(unsigned)__shfl_sync(0xffffffffu, mykey, r + 3);
            float4 f0 = ((const float4*)(Fb + (size_t)n0 * NCH))[lane];
            float4 f1 = ((const float4*)(Fb + (size_t)n1 * NCH))[lane];
            float4 f2 = ((const float4*)(Fb + (size_t)n2 * NCH))[lane];
            float4 f3 = ((const float4*)(Fb + (size_t)n3 * NCH))[lane];
            acc.x += f0.x; acc.y += f0.y; acc.z += f0.z; acc.w += f0.w;
            acc.x += f1.x; acc.y += f1.y; acc.z += f1.z; acc.w += f1.w;
            acc.x += f2.x; acc.y += f2.y; acc.z += f2.z; acc.w += f2.w;
            acc.x += f3.x; acc.y += f3.y; acc.z += f3.z; acc.w += f3.w;
        }
        float4 o = make_float4(acc.x * 0.0625f, acc.y * 0.0625f,
                               acc.z * 0.0625f, acc.w * 0.0625f);
        ((float4*)(g_coarse_t + (size_t)gw * NCH))[lane] = o;
    }
}

// ---------------- three_nn part: 4 chunks x 512 queries, fused gather, lex top-3 ----------------
__global__ void __launch_bounds__(256) three_nn_part() {
    int b = blockIdx.y, c = blockIdx.z;
    int n = blockIdx.x * 256 + threadIdx.x;
    __shared__ float4 sq4[512];
    for (int i = threadIdx.x; i < 512; i += 256)
        sq4[i] = g_p4[b * NPTS + g_fps[b * NPQ + c * 512 + i]];   // fused gather
    __syncthreads();

    float4 p = g_p4[b * NPTS + n];
    u64 k0 = ~0ull, k1 = ~0ull, k2 = ~0ull;
    for (int j2 = 0; j2 < 512; j2++) {
        float4 q = sq4[j2];
        float dot = __fmaf_rn(q.z, p.z, __fmaf_rn(q.y, p.y, q.x * p.x));
        float s   = fmaxf(__fmaf_rn(-2.f, dot, q.w + p.w), 0.f);
        u64 key = ((u64)__float_as_uint(s) << 32) | (unsigned)(c * 512 + j2);
        if (key < k2) {
            if (key < k0)      { k2 = k1; k1 = k0; k0 = key; }
            else if (key < k1) { k2 = k1; k1 = key; }
            else               { k2 = key; }
        }
    }
    size_t o = ((size_t)(b * NPTS + n) * 4 + c) * 3;
    g_nn[o] = k0; g_nn[o + 1] = k1; g_nn[o + 2] = k2;
}

// ---------------- three_nn combine: merge 4 chunks, compute weights ----------------
__global__ void __launch_bounds__(256) three_nn_comb() {
    int i = blockIdx.x * 256 + threadIdx.x;           // over NB*NPTS
    u64 a0 = ~0ull, a1 = ~0ull, a2 = ~0ull;
#pragma unroll
    for (int c = 0; c < 12; c++) {
        u64 k = g_nn[(size_t)i * 12 + c];
        if (k < a0)      { a2 = a1; a1 = a0; a0 = k; }
        else if (k < a1) { a2 = a1; a1 = k; }
        else if (k < a2) { a2 = k; }
    }
    float d0 = fmaxf(__uint_as_float((unsigned)(a0 >> 32)), 1e-10f);
    float d1 = fmaxf(__uint_as_float((unsigned)(a1 >> 32)), 1e-10f);
    float d2 = fmaxf(__uint_as_float((unsigned)(a2 >> 32)), 1e-10f);
    float v0 = __fdiv_rn(1.f, d0 + 1e-8f);
    float v1 = __fdiv_rn(1.f, d1 + 1e-8f);
    float v2 = __fdiv_rn(1.f, d2 + 1e-8f);
    float ss = v0 + v1 + v2;
    int o = i * 3;
    g_i3[o] = (int)(unsigned)a0; g_i3[o + 1] = (int)(unsigned)a1; g_i3[o + 2] = (int)(unsigned)a2;
    g_w3[o]     = __fdiv_rn(v0, ss);
    g_w3[o + 1] = __fdiv_rn(v1, ss);
    g_w3[o + 2] = __fdiv_rn(v2, ss);
}

// ---------------- interpolate: smem-staged, coalesced channel-major stores ----------------
__global__ void __launch_bounds__(256) interp_kernel(float* __restrict__ out) {
    __shared__ float tile[32 * 129];
    int b    = blockIdx.y;
    int n0   = blockIdx.x * 32;
    int lane = threadIdx.x & 31;
    int w    = threadIdx.x >> 5;

#pragma unroll
    for (int k = 0; k < 4; k++) {
        int nl = w * 4 + k;
        int n  = n0 + nl;
        int o = (b * NPTS + n) * 3;
        int a0 = g_i3[o], a1 = g_i3[o + 1], a2 = g_i3[o + 2];
        float w0 = g_w3[o], w1 = g_w3[o + 1], w2 = g_w3[o + 2];

        const float4* C = (const float4*)g_coarse_t + (size_t)b * NPQ * (NCH / 4);
        float4 f0 = C[a0 * (NCH / 4) + lane];
        float4 f1 = C[a1 * (NCH / 4) + lane];
        float4 f2 = C[a2 * (NCH / 4) + lane];

        float4 r;
        r.x = __fmaf_rn(f2.x, w2, __fmaf_rn(f1.x, w1, f0.x * w0));
        r.y = __fmaf_rn(f2.y, w2, __fmaf_rn(f1.y, w1, f0.y * w0));
        r.z = __fmaf_rn(f2.z, w2, __fmaf_rn(f1.z, w1, f0.z * w0));
        r.w = __fmaf_rn(f2.w, w2, __fmaf_rn(f1.w, w1, f0.w * w0));

        float* trow = tile + nl * 129 + lane * 4;
        trow[0] = r.x; trow[1] = r.y; trow[2] = r.z; trow[3] = r.w;
    }
    __syncthreads();

    float* ob = out + (size_t)b * NCH * NPTS + n0;
#pragma unroll
    for (int pass = 0; pass < 16; pass++) {
        int c = pass * 8 + w;
        ob[(size_t)c * NPTS + lane] = tile[lane * 129 + c];
    }
}

// ---------------- launch ----------------
extern "C" void kernel_launch(void* const* d_in, const int* in_sizes, int n_in,
                              void* d_out, int out_size) {
    const float* points   = (const float*)d_in[0];
    const float* features = (const float*)d_in[1];
    for (int i = 0; i < n_in; i++) {
        if (in_sizes[i] == NB * NPTS * 3)            points   = (const float*)d_in[i];
        else if (in_sizes[i] == NB * NCH * NPTS)     features = (const float*)d_in[i];
    }
    float* out = (float*)d_out;

    const int fps_smem = NPTS * (int)sizeof(float4) + NPTS * (int)sizeof(int); // 160KB
    const int knn_smem = NPTS * (int)sizeof(float4);                           // 128KB
    cudaFuncSetAttribute(fps_kernel,       cudaFuncAttributeMaxDynamicSharedMemorySize, fps_smem);
    cudaFuncSetAttribute(knn_group_kernel, cudaFuncAttributeMaxDynamicSharedMemorySize, knn_smem);

    prep_sort_kernel<<<NB, 1024>>>(points);                                 // 1
    fps_kernel<<<NB, 512, fps_smem>>>();                                    // 2
    transpose_kernel<<<dim3(NPTS / 32, NCH / 32, NB), dim3(32, 32)>>>(features); // 3
    knn_group_kernel<<<128, 1024, knn_smem>>>();                            // 4 <- profiled
    three_nn_part<<<dim3(NPTS / 256, NB, 4), 256>>>();                      // 5
    three_nn_comb<<<(NB * NPTS) / 256, 256>>>();                            // 6
    interp_kernel<<<dim3(NPTS / 32, NB), 256>>>(out);                       // 7
}

// round 17
// speedup vs baseline: 1.0897x; 1.0249x over previous
#include <cuda_runtime.h>
#include <cstdint>
#include <float.h>

#define NB    4
#define NPTS  8192
#define NPQ   2048
#define NCH   128

// ---------------- device scratch (statically allocated; no cudaMalloc) ----------------
__device__ float4 g_p4[NB * NPTS];                    // (x,y,z,|p|^2)
__device__ int    g_fps[NB * NPQ];
__device__ int    g_ord[NB * NPTS];                   // morton-binned original indices
__device__ float  g_feat_t[(size_t)NB * NPTS * NCH];  // features transposed [B,N,C]
__device__ float  g_coarse_t[(size_t)NB * NPQ * NCH]; // pooled features [B,q,C]

typedef unsigned long long u64;
__device__ u64 g_nn[(size_t)NB * NPTS * 12];          // three_nn partials: 4 chunks x 3 keys

// ---------------- packed f32x2 helpers ----------------
__device__ __forceinline__ u64 pk2(float a, float b) {
    u64 r; asm("mov.b64 %0, {%1,%2};" : "=l"(r) : "f"(a), "f"(b)); return r;
}
__device__ __forceinline__ void upk2(u64 v, float& a, float& b) {
    asm("mov.b64 {%0,%1}, %2;" : "=f"(a), "=f"(b) : "l"(v));
}
__device__ __forceinline__ u64 add2(u64 a, u64 b) {
    u64 r; asm("add.rn.f32x2 %0, %1, %2;" : "=l"(r) : "l"(a), "l"(b)); return r;
}
__device__ __forceinline__ u64 mul2(u64 a, u64 b) {
    u64 r; asm("mul.rn.f32x2 %0, %1, %2;" : "=l"(r) : "l"(a), "l"(b)); return r;
}
__device__ __forceinline__ u64 fma2(u64 a, u64 b, u64 c) {
    u64 r; asm("fma.rn.f32x2 %0, %1, %2, %3;" : "=l"(r) : "l"(a), "l"(b), "l"(c)); return r;
}

// ---------------- merged prep + morton counting sort (one CTA per batch) ----------------
__device__ __forceinline__ unsigned eb4(unsigned v) {  // 4 bits -> stride-3 positions
    return (v & 1u) | ((v & 2u) << 2) | ((v & 4u) << 4) | ((v & 8u) << 6);
}
__global__ void __launch_bounds__(1024, 1) prep_sort_kernel(const float* __restrict__ pts) {
    __shared__ unsigned hist[4096];
    __shared__ unsigned wsum[32];
    const int b = blockIdx.x, tid = threadIdx.x;
    const int lane = tid & 31, wid = tid >> 5;
    for (int i = tid; i < 4096; i += 1024) hist[i] = 0;
    __syncthreads();
    unsigned code[8];
#pragma unroll
    for (int k = 0; k < 8; k++) {
        int i = b * NPTS + tid + k * 1024;
        float x = pts[3 * i], y = pts[3 * i + 1], z = pts[3 * i + 2];
        float nr = __fmaf_rn(z, z, __fmaf_rn(y, y, x * x));
        g_p4[i] = make_float4(x, y, z, nr);
        unsigned mx = (unsigned)fminf(fmaxf((x + 4.f) * 2.f, 0.f), 15.f);
        unsigned my = (unsigned)fminf(fmaxf((y + 4.f) * 2.f, 0.f), 15.f);
        unsigned mz = (unsigned)fminf(fmaxf((z + 4.f) * 2.f, 0.f), 15.f);
        code[k] = eb4(mx) | (eb4(my) << 1) | (eb4(mz) << 2);
        atomicAdd(&hist[code[k]], 1u);
    }
    __syncthreads();
    unsigned h0 = hist[4 * tid], h1 = hist[4 * tid + 1],
             h2 = hist[4 * tid + 2], h3 = hist[4 * tid + 3];
    unsigned s = h0 + h1 + h2 + h3, si = s;
#pragma unroll
    for (int d = 1; d < 32; d <<= 1) {
        unsigned v = __shfl_up_sync(0xffffffffu, si, d);
        if (lane >= d) si += v;
    }
    if (lane == 31) wsum[wid] = si;
    __syncthreads();
    if (wid == 0) {
        unsigned v = wsum[lane], vi = v;
#pragma unroll
        for (int d = 1; d < 32; d <<= 1) {
            unsigned t = __shfl_up_sync(0xffffffffu, vi, d);
            if (lane >= d) vi += t;
        }
        wsum[lane] = vi;
    }
    __syncthreads();
    unsigned base = (wid ? wsum[wid - 1] : 0u) + si - s;
    hist[4 * tid]     = base;
    hist[4 * tid + 1] = base + h0;
    hist[4 * tid + 2] = base + h0 + h1;
    hist[4 * tid + 3] = base + h0 + h1 + h2;
    __syncthreads();
#pragma unroll
    for (int k = 0; k < 8; k++) {
        int i = tid + k * 1024;
        unsigned slot = atomicAdd(&hist[code[k]], 1u);
        g_ord[b * NPTS + slot] = i;
    }
}

// ---------------- FPS: 512 threads x 16 pts, per-warp HALF-chunk pruning ----------------
// Two sub-boxes per warp (256 sorted pts each). A half updates only if its
// boxdist2 < wmax*1.00001 (conservative margin >> fp rounding of the frozen
// subtract-form fma chain). Tie rule = lowest original index everywhere.
__global__ void __launch_bounds__(512, 1) fps_kernel() {
    extern __shared__ char fsmem[];                   // sP 128KB | sOrd 32KB
    float4* sP   = (float4*)fsmem;
    int*    sOrd = (int*)(fsmem + NPTS * sizeof(float4));
    const int b    = blockIdx.x;
    const int tid  = threadIdx.x;
    const int lane = tid & 31;
    const int wid  = tid >> 5;                        // 0..15
    const float4* __restrict__ P = g_p4 + b * NPTS;

#pragma unroll
    for (int k = 0; k < 16; k++) {
        sP[tid + k * 512]   = P[tid + k * 512];
        sOrd[tid + k * 512] = g_ord[b * NPTS + tid + k * 512];
    }
    __shared__ u64 skey[2][16];
    if (tid == 0) g_fps[b * NPQ] = 0;
    __syncthreads();

    const int wbase = wid * 512 + lane * 2;
    u64 X[8], Y[8], Z[8];
    float dist[16];
    unsigned ordp[8];
    // per-half bounding boxes (groups 0-3 -> half0, 4-7 -> half1)
    float bl[2][3], bh[2][3];
#pragma unroll
    for (int h = 0; h < 2; h++) {
        bl[h][0] = bl[h][1] = bl[h][2] = FLT_MAX;
        bh[h][0] = bh[h][1] = bh[h][2] = -FLT_MAX;
    }
#pragma unroll
    for (int i = 0; i < 8; i++) {
        int o0 = sOrd[wbase + i * 64], o1 = sOrd[wbase + i * 64 + 1];
        ordp[i] = (unsigned)o0 | ((unsigned)o1 << 16);
        float4 a = sP[o0], c = sP[o1];
        X[i] = pk2(a.x, c.x); Y[i] = pk2(a.y, c.y); Z[i] = pk2(a.z, c.z);
        int h = i >> 2;
        bl[h][0] = fminf(bl[h][0], fminf(a.x, c.x)); bh[h][0] = fmaxf(bh[h][0], fmaxf(a.x, c.x));
        bl[h][1] = fminf(bl[h][1], fminf(a.y, c.y)); bh[h][1] = fmaxf(bh[h][1], fmaxf(a.y, c.y));
        bl[h][2] = fminf(bl[h][2], fminf(a.z, c.z)); bh[h][2] = fmaxf(bh[h][2], fmaxf(a.z, c.z));
    }
#pragma unroll
    for (int h = 0; h < 2; h++)
#pragma unroll
        for (int s = 16; s > 0; s >>= 1) {
            bl[h][0] = fminf(bl[h][0], __shfl_xor_sync(0xffffffffu, bl[h][0], s));
            bh[h][0] = fmaxf(bh[h][0], __shfl_xor_sync(0xffffffffu, bh[h][0], s));
            bl[h][1] = fminf(bl[h][1], __shfl_xor_sync(0xffffffffu, bl[h][1], s));
            bh[h][1] = fmaxf(bh[h][1], __shfl_xor_sync(0xffffffffu, bh[h][1], s));
            bl[h][2] = fminf(bl[h][2], __shfl_xor_sync(0xffffffffu, bl[h][2], s));
            bh[h][2] = fmaxf(bh[h][2], __shfl_xor_sync(0xffffffffu, bh[h][2], s));
        }

    u64 mykey;
    float wmaxf, htmax0, htmax1;
    {   // iteration 0: d0 = ||x - x0||^2 (reference's exact fma chain)
        float4 q0 = sP[0];
        u64 ax = pk2(-q0.x, -q0.x), ay = pk2(-q0.y, -q0.y), az = pk2(-q0.z, -q0.z);
#pragma unroll
        for (int i = 0; i < 8; i++) {
            u64 dx = add2(X[i], ax), dy = add2(Y[i], ay), dz = add2(Z[i], az);
            u64 t = fma2(dz, dz, fma2(dy, dy, mul2(dx, dx)));
            upk2(t, dist[2 * i], dist[2 * i + 1]);
        }
        htmax0 = dist[0]; htmax1 = dist[8];
#pragma unroll
        for (int k = 1; k < 8; k++) {
            htmax0 = fmaxf(htmax0, dist[k]);
            htmax1 = fmaxf(htmax1, dist[8 + k]);
        }
        float tmax = fmaxf(htmax0, htmax1);
        unsigned wm = __reduce_max_sync(0xffffffffu, __float_as_uint(tmax));
        wmaxf = __uint_as_float(wm);
        unsigned cand = 0xffffffffu;
#pragma unroll
        for (int k = 0; k < 16; k++) {
            unsigned oi = (k & 1) ? (ordp[k >> 1] >> 16) : (ordp[k >> 1] & 0xffffu);
            if (dist[k] == wmaxf) cand = min(cand, oi);
        }
        unsigned widx = __reduce_min_sync(0xffffffffu, cand);
        mykey = ((u64)wm << 32) | widx;
        if (lane == 0) skey[0][wid] = mykey;
    }

    for (int j = 1; j < NPQ; j++) {
        __syncthreads();
        u64 k64 = skey[(j - 1) & 1][lane & 15];
        unsigned hi = (unsigned)(k64 >> 32), lo = (unsigned)k64;
        unsigned g   = __reduce_max_sync(0xffffffffu, hi);
        unsigned cc  = (hi == g) ? lo : 0xffffffffu;
        unsigned nxt = __reduce_min_sync(0xffffffffu, cc);
        if (tid == 0) g_fps[b * NPQ + j] = (int)nxt;

        float4 qq = sP[nxt];
        float thr = wmaxf * 1.00001f;
        float d0x = fmaxf(fmaxf(bl[0][0] - qq.x, qq.x - bh[0][0]), 0.f);
        float d0y = fmaxf(fmaxf(bl[0][1] - qq.y, qq.y - bh[0][1]), 0.f);
        float d0z = fmaxf(fmaxf(bl[0][2] - qq.z, qq.z - bh[0][2]), 0.f);
        float bd0 = __fmaf_rn(d0z, d0z, __fmaf_rn(d0y, d0y, d0x * d0x));
        float d1x = fmaxf(fmaxf(bl[1][0] - qq.x, qq.x - bh[1][0]), 0.f);
        float d1y = fmaxf(fmaxf(bl[1][1] - qq.y, qq.y - bh[1][1]), 0.f);
        float d1z = fmaxf(fmaxf(bl[1][2] - qq.z, qq.z - bh[1][2]), 0.f);
        float bd1 = __fmaf_rn(d1z, d1z, __fmaf_rn(d1y, d1y, d1x * d1x));
        bool c0 = bd0 < thr, c1 = bd1 < thr;

        if (c0 | c1) {
            u64 ax = pk2(-qq.x, -qq.x), ay = pk2(-qq.y, -qq.y), az = pk2(-qq.z, -qq.z);
            if (c0) {
#pragma unroll
                for (int i = 0; i < 4; i++) {
                    u64 dx = add2(X[i], ax), dy = add2(Y[i], ay), dz = add2(Z[i], az);
                    u64 t = fma2(dz, dz, fma2(dy, dy, mul2(dx, dx)));
                    float a, c; upk2(t, a, c);
                    dist[2 * i]     = fminf(dist[2 * i], a);
                    dist[2 * i + 1] = fminf(dist[2 * i + 1], c);
                }
                htmax0 = dist[0];
#pragma unroll
                for (int k = 1; k < 8; k++) htmax0 = fmaxf(htmax0, dist[k]);
            }
            if (c1) {
#pragma unroll
                for (int i = 4; i < 8; i++) {
                    u64 dx = add2(X[i], ax), dy = add2(Y[i], ay), dz = add2(Z[i], az);
                    u64 t = fma2(dz, dz, fma2(dy, dy, mul2(dx, dx)));
                    float a, c; upk2(t, a, c);
                    dist[2 * i]     = fminf(dist[2 * i], a);
                    dist[2 * i + 1] = fminf(dist[2 * i + 1], c);
                }
                htmax1 = dist[8];
#pragma unroll
                for (int k = 1; k < 8; k++) htmax1 = fmaxf(htmax1, dist[8 + k]);
            }
            float tmax = fmaxf(htmax0, htmax1);
            unsigned wm = __reduce_max_sync(0xffffffffu, __float_as_uint(tmax));
            wmaxf = __uint_as_float(wm);
            unsigned cand = 0xffffffffu;
#pragma unroll
            for (int k = 0; k < 16; k++) {
                unsigned oi = (k & 1) ? (ordp[k >> 1] >> 16) : (ordp[k >> 1] & 0xffffu);
                if (dist[k] == wmaxf) cand = min(cand, oi);
            }
            unsigned widx = __reduce_min_sync(0xffffffffu, cand);
            mykey = ((u64)wm << 32) | widx;
        }
        if (lane == 0) skey[j & 1][wid] = mykey;
    }
}

// ---------------- transpose features [B,C,N] -> [B,N,C] ----------------
__global__ void transpose_kernel(const float* __restrict__ f) {
    __shared__ float tile[32][33];
    int b = blockIdx.z;
    int c0 = blockIdx.y * 32, n0 = blockIdx.x * 32;
    tile[threadIdx.y][threadIdx.x] =
        f[((size_t)b * NCH + c0 + threadIdx.y) * NPTS + n0 + threadIdx.x];
    __syncthreads();
    g_feat_t[((size_t)b * NPTS + n0 + threadIdx.y) * NCH + c0 + threadIdx.x] =
        tile[threadIdx.x][threadIdx.y];
}

// ---------------- kNN: warp-shared sorted top-17 + mean-pool (R14/R16, frozen) ----------------
__global__ void __launch_bounds__(1024) knn_group_kernel() {
    extern __shared__ float4 sT[];                    // 8192 float4 = 128KB
    const int tid  = threadIdx.x;
    const int lane = tid & 31;
    const int w    = tid >> 5;
    const int b    = blockIdx.x >> 5;
    const int qb   = (blockIdx.x & 31) * 64;

#pragma unroll
    for (int k = 0; k < 8; k++) sT[tid + k * 1024] = g_p4[b * NPTS + tid + k * 1024];
    __syncthreads();

    const float* Fb = g_feat_t + (size_t)b * NPTS * NCH;
    for (int qi = 0; qi < 2; qi++) {
        int gw = b * NPQ + qb + w * 2 + qi;
        float4 q = sT[g_fps[gw]];
        u64 mykey = 0x7F7FFFFFFFFFFFFFull;            // (FLT_MAX, ~0)
        float thr_f = FLT_MAX;
        for (int t = 0; t < NPTS / 32; t++) {
            int n = t * 32 + lane;
            float4 p = sT[n];
            float dot = __fmaf_rn(q.z, p.z, __fmaf_rn(q.y, p.y, q.x * p.x));
            float sq  = fmaxf(__fmaf_rn(-2.f, dot, q.w + p.w), 0.f);
            unsigned ball = __ballot_sync(0xffffffffu, sq < thr_f);
            if (ball) {
                u64 cand = ((u64)__float_as_uint(sq) << 32) | (unsigned)n;
                do {
                    int src = __ffs(ball) - 1; ball &= ball - 1;
                    u64 c = __shfl_sync(0xffffffffu, cand, src);
                    unsigned pb = __ballot_sync(0xffffffffu, (lane < 17) && (c < mykey));
                    if (pb) {
                        int pos = __ffs(pb) - 1;
                        u64 up = __shfl_up_sync(0xffffffffu, mykey, 1);
                        if (lane >= pos && lane < 17) mykey = (lane == pos) ? c : up;
                    }
                } while (ball);
                thr_f = __uint_as_float(
                    __shfl_sync(0xffffffffu, (unsigned)(mykey >> 32), 16));
            }
        }
        float4 acc = make_float4(0.f, 0.f, 0.f, 0.f);
#pragma unroll
        for (int r = 1; r < 17; r += 4) {
            int n0 = (int)(unsigned)__shfl_sync(0xffffffffu, mykey, r);
            int n1 = (int)(unsigned)__shfl_sync(0xffffffffu, mykey, r + 1);
            int n2 = (int)(unsigned)__shfl_sync(0xffffffffu, mykey, r + 2);
            int n3 = (int)(unsigned)__shfl_sync(0xffffffffu, mykey, r + 3);
            float4 f0 = ((const float4*)(Fb + (size_t)n0 * NCH))[lane];
            float4 f1 = ((const float4*)(Fb + (size_t)n1 * NCH))[lane];
            float4 f2 = ((const float4*)(Fb + (size_t)n2 * NCH))[lane];
            float4 f3 = ((const float4*)(Fb + (size_t)n3 * NCH))[lane];
            acc.x += f0.x; acc.y += f0.y; acc.z += f0.z; acc.w += f0.w;
            acc.x += f1.x; acc.y += f1.y; acc.z += f1.z; acc.w += f1.w;
            acc.x += f2.x; acc.y += f2.y; acc.z += f2.z; acc.w += f2.w;
            acc.x += f3.x; acc.y += f3.y; acc.z += f3.z; acc.w += f3.w;
        }
        float4 o = make_float4(acc.x * 0.0625f, acc.y * 0.0625f,
                               acc.z * 0.0625f, acc.w * 0.0625f);
        ((float4*)(g_coarse_t + (size_t)gw * NCH))[lane] = o;
    }
}

// ---------------- three_nn part: float-threshold admit, exact lex insert ----------------
__global__ void __launch_bounds__(256) three_nn_part() {
    int b = blockIdx.y, c = blockIdx.z;
    int n = blockIdx.x * 256 + threadIdx.x;
    __shared__ float4 sq4[512];
    for (int i = threadIdx.x; i < 512; i += 256)
        sq4[i] = g_p4[b * NPTS + g_fps[b * NPQ + c * 512 + i]];   // fused gather
    __syncthreads();

    float4 p = g_p4[b * NPTS + n];
    u64 k0 = 0x7F7FFFFFFFFFFFFFull, k1 = k0, k2 = k0;             // (FLT_MAX, ~0)
    float thr2 = FLT_MAX;
    for (int j2 = 0; j2 < 512; j2++) {
        float4 q = sq4[j2];
        float dot = __fmaf_rn(q.z, p.z, __fmaf_rn(q.y, p.y, q.x * p.x));
        float s   = fmaxf(__fmaf_rn(-2.f, dot, q.w + p.w), 0.f);
        if (s <= thr2) {                                          // rare path
            u64 key = ((u64)__float_as_uint(s) << 32) | (unsigned)(c * 512 + j2);
            if (key < k2) {
                if (key < k0)      { k2 = k1; k1 = k0; k0 = key; }
                else if (key < k1) { k2 = k1; k1 = key; }
                else               { k2 = key; }
                thr2 = __uint_as_float((unsigned)(k2 >> 32));
            }
        }
    }
    size_t o = ((size_t)(b * NPTS + n) * 4 + c) * 3;
    g_nn[o] = k0; g_nn[o + 1] = k1; g_nn[o + 2] = k2;
}

// ---------------- interpolate: fused chunk-merge + smem-staged coalesced stores ----------------
__global__ void __launch_bounds__(256) interp_kernel(float* __restrict__ out) {
    __shared__ float tile[32 * 129];
    __shared__ int   si3[32][3];
    __shared__ float sw3[32][3];
    int b    = blockIdx.y;
    int n0   = blockIdx.x * 32;
    int lane = threadIdx.x & 31;
    int w    = threadIdx.x >> 5;

    if (threadIdx.x < 32) {                           // merge 12 lex keys per point
        int n = n0 + threadIdx.x;
        const u64* nn = g_nn + (size_t)(b * NPTS + n) * 12;
        u64 a0 = ~0ull, a1 = ~0ull, a2 = ~0ull;
#pragma unroll
        for (int c = 0; c < 12; c++) {
            u64 k = nn[c];
            if (k < a0)      { a2 = a1; a1 = a0; a0 = k; }
            else if (k < a1) { a2 = a1; a1 = k; }
            else if (k < a2) { a2 = k; }
        }
        float d0 = fmaxf(__uint_as_float((unsigned)(a0 >> 32)), 1e-10f);
        float d1 = fmaxf(__uint_as_float((unsigned)(a1 >> 32)), 1e-10f);
        float d2 = fmaxf(__uint_as_float((unsigned)(a2 >> 32)), 1e-10f);
        float v0 = __fdiv_rn(1.f, d0 + 1e-8f);
        float v1 = __fdiv_rn(1.f, d1 + 1e-8f);
        float v2 = __fdiv_rn(1.f, d2 + 1e-8f);
        float ss = v0 + v1 + v2;
        si3[threadIdx.x][0] = (int)(unsigned)a0;
        si3[threadIdx.x][1] = (int)(unsigned)a1;
        si3[threadIdx.x][2] = (int)(unsigned)a2;
        sw3[threadIdx.x][0] = __fdiv_rn(v0, ss);
        sw3[threadIdx.x][1] = __fdiv_rn(v1, ss);
        sw3[threadIdx.x][2] = __fdiv_rn(v2, ss);
    }
    __syncthreads();

#pragma unroll
    for (int k = 0; k < 4; k++) {
        int nl = w * 4 + k;
        int a0 = si3[nl][0], a1 = si3[nl][1], a2 = si3[nl][2];
        float w0 = sw3[nl][0], w1 = sw3[nl][1], w2 = sw3[nl][2];

        const float4* C = (const float4*)g_coarse_t + (size_t)b * NPQ * (NCH / 4);
        float4 f0 = C[a0 * (NCH / 4) + lane];
        float4 f1 = C[a1 * (NCH / 4) + lane];
        float4 f2 = C[a2 * (NCH / 4) + lane];

        float4 r;
        r.x = __fmaf_rn(f2.x, w2, __fmaf_rn(f1.x, w1, f0.x * w0));
        r.y = __fmaf_rn(f2.y, w2, __fmaf_rn(f1.y, w1, f0.y * w0));
        r.z = __fmaf_rn(f2.z, w2, __fmaf_rn(f1.z, w1, f0.z * w0));
        r.w = __fmaf_rn(f2.w, w2, __fmaf_rn(f1.w, w1, f0.w * w0));

        float* trow = tile + nl * 129 + lane * 4;
        trow[0] = r.x; trow[1] = r.y; trow[2] = r.z; trow[3] = r.w;
    }
    __syncthreads();

    float* ob = out + (size_t)b * NCH * NPTS + n0;
#pragma unroll
    for (int pass = 0; pass < 16; pass++) {
        int c = pass * 8 + w;
        ob[(size_t)c * NPTS + lane] = tile[lane * 129 + c];
    }
}

// ---------------- launch ----------------
extern "C" void kernel_launch(void* const* d_in, const int* in_sizes, int n_in,
                              void* d_out, int out_size) {
    const float* points   = (const float*)d_in[0];
    const float* features = (const float*)d_in[1];
    for (int i = 0; i < n_in; i++) {
        if (in_sizes[i] == NB * NPTS * 3)            points   = (const float*)d_in[i];
        else if (in_sizes[i] == NB * NCH * NPTS)     features = (const float*)d_in[i];
    }
    float* out = (float*)d_out;

    const int fps_smem = NPTS * (int)sizeof(float4) + NPTS * (int)sizeof(int); // 160KB
    const int knn_smem = NPTS * (int)sizeof(float4);                           // 128KB
    cudaFuncSetAttribute(fps_kernel,       cudaFuncAttributeMaxDynamicSharedMemorySize, fps_smem);
    cudaFuncSetAttribute(knn_group_kernel, cudaFuncAttributeMaxDynamicSharedMemorySize, knn_smem);

    prep_sort_kernel<<<NB, 1024>>>(points);                                 // 1
    fps_kernel<<<NB, 512, fps_smem>>>();                                    // 2
    transpose_kernel<<<dim3(NPTS / 32, NCH / 32, NB), dim3(32, 32)>>>(features); // 3
    knn_group_kernel<<<128, 1024, knn_smem>>>();                            // 4 <- profiled
    three_nn_part<<<dim3(NPTS / 256, NB, 4), 256>>>();                      // 5
    interp_kernel<<<dim3(NPTS / 32, NB), 256>>>(out);                       // 6
}